// round 14
// baseline (speedup 1.0000x reference)
#include <cuda_runtime.h>
#include <cuda_bf16.h>
#include <math.h>

// ---------------- problem constants ----------------
#define T_DIM 4096
#define D_DIM 2048
#define H_DIM 16
#define NOPE 128
#define ROPE 64
#define VD 128
#define KV_RANK 512
#define HEAD 192               // NOPE + ROPE
#define Q_RANK 1536
#define B_DIM 2
#define S_DIM 2048
#define SCALE_F 0.072168783648703220563f   // 192^-0.5
#define EPS_F 1e-6f

// ---------------- scratch ----------------
__device__ float g_qa  [(long long)T_DIM * Q_RANK];
__device__ float g_qan [(long long)T_DIM * Q_RANK];
__device__ float g_q   [(long long)T_DIM * H_DIM * HEAD];
__device__ float g_ckv [(long long)T_DIM * (KV_RANK + ROPE)];
__device__ float g_ckvn[(long long)T_DIM * KV_RANK];
__device__ float g_kv  [(long long)T_DIM * H_DIM * (NOPE + VD)];
__device__ float g_key [(long long)T_DIM * H_DIM * HEAD];
__device__ float g_attn[(long long)T_DIM * H_DIM * VD];
// transposed (tf32-rounded) weights / V
__device__ float g_wqaT [(long long)Q_RANK * D_DIM];
__device__ float g_wqbT [(long long)H_DIM * HEAD * Q_RANK];
__device__ float g_wkvaT[(long long)(KV_RANK + ROPE) * D_DIM];
__device__ float g_wkvbT[(long long)H_DIM * (NOPE + VD) * KV_RANK];
__device__ float g_woT  [(long long)D_DIM * H_DIM * VD];
__device__ float g_vT   [(long long)B_DIM * H_DIM * VD * S_DIM];

__device__ __forceinline__ float tf32f(float f) {
    unsigned u; asm("cvt.rna.tf32.f32 %0, %1;" : "=r"(u) : "f"(f));
    return __uint_as_float(u);
}
__device__ __forceinline__ unsigned tf32r(unsigned u) {
    unsigned o; asm("cvt.rna.tf32.f32 %0, %1;" : "=r"(o) : "f"(__uint_as_float(u)));
    return o;
}
__device__ __forceinline__ void cp16(unsigned dst, const void* src) {
    asm volatile("cp.async.cg.shared.global [%0], [%1], 16;\n"
                 :: "r"(dst), "l"(src));
}
__device__ __forceinline__ void ldsm4(unsigned& r0, unsigned& r1, unsigned& r2, unsigned& r3,
                                      unsigned addr) {
    asm volatile("ldmatrix.sync.aligned.m8n8.x4.shared.b16 {%0,%1,%2,%3}, [%4];"
                 : "=r"(r0), "=r"(r1), "=r"(r2), "=r"(r3) : "r"(addr));
}
#define MMA_TF32(acc, a, b0, b1) \
    asm volatile("mma.sync.aligned.m16n8k8.row.col.f32.tf32.tf32.f32 " \
                 "{%0,%1,%2,%3},{%4,%5,%6,%7},{%8,%9},{%0,%1,%2,%3};" \
                 : "+f"(acc[0]), "+f"(acc[1]), "+f"(acc[2]), "+f"(acc[3]) \
                 : "r"(a[0]), "r"(a[1]), "r"(a[2]), "r"(a[3]), "r"(b0), "r"(b1))

// ---------------- NT tf32 GEMM body (R12 proven): 128x64x32, 4 warps, 2 stages, frag-db -----
#define STG_B 27648
#define BOFF_B 18432

__device__ __forceinline__ void gemm_body(
    const float* __restrict__ A, const float* __restrict__ B, float* __restrict__ C,
    int K, int lda, int ldb, int ldc, int m0, int n0, int round_out, int round_a, char* smc)
{
    float* sm = (float*)smc;
    int nIter = K >> 5;
    int tid  = threadIdx.x;
    int lane = tid & 31;
    int wid  = tid >> 5;
    int wm   = wid & 1;
    int wn   = wid >> 1;

    unsigned sbase = (unsigned)__cvta_generic_to_shared(sm);
    int lrow = tid >> 3;
    int lc   = tid & 7;

    auto issue = [&](int itk) {
        int k0 = itk << 5;
        unsigned sb = sbase + (unsigned)(itk & 1) * STG_B;
        const float* Ap = A + (long long)(m0 + lrow) * lda + k0 + lc * 4;
        unsigned ad = sb + lrow * 144 + lc * 16;
#pragma unroll
        for (int it = 0; it < 8; it++)
            cp16(ad + it * (16 * 144), Ap + (long long)(it * 16) * lda);
        const float* Bp = B + (long long)(n0 + lrow) * ldb + k0 + lc * 4;
        unsigned bd = sb + BOFF_B + lrow * 144 + lc * 16;
#pragma unroll
        for (int it = 0; it < 4; it++)
            cp16(bd + it * (16 * 144), Bp + (long long)(it * 16) * ldb);
        asm volatile("cp.async.commit_group;");
    };

    issue(0);

    unsigned aoff[4], boff[2];
#pragma unroll
    for (int i = 0; i < 4; i++) {
        int R = wm * 64 + i * 16 + (lane & 15);
        aoff[i] = (unsigned)(R * 144 + (lane >> 4) * 16);
    }
#pragma unroll
    for (int jp = 0; jp < 2; jp++) {
        int R = wn * 32 + jp * 16 + ((lane >> 4) & 1) * 8 + (lane & 7);
        boff[jp] = (unsigned)(BOFF_B + R * 144 + ((lane >> 3) & 1) * 16);
    }

    float acc[4][4][4];
#pragma unroll
    for (int i = 0; i < 4; i++)
#pragma unroll
        for (int j = 0; j < 4; j++)
#pragma unroll
            for (int r = 0; r < 4; r++) acc[i][j][r] = 0.f;

    unsigned af[2][4][4], bf[2][2][4];

    auto rndA = [&](int buf) {
        if (round_a) {
#pragma unroll
            for (int ii = 0; ii < 4; ii++)
#pragma unroll
                for (int r = 0; r < 4; r++) af[buf][ii][r] = tf32r(af[buf][ii][r]);
        }
    };

    for (int i = 0; i < nIter; i++) {
        if (i + 1 < nIter) {
            issue(i + 1);
            asm volatile("cp.async.wait_group 1;");
        } else {
            asm volatile("cp.async.wait_group 0;");
        }
        __syncthreads();

        unsigned sb = sbase + (unsigned)(i & 1) * STG_B;
#pragma unroll
        for (int ii = 0; ii < 4; ii++)
            ldsm4(af[0][ii][0], af[0][ii][1], af[0][ii][2], af[0][ii][3], sb + aoff[ii]);
        rndA(0);
#pragma unroll
        for (int jp = 0; jp < 2; jp++)
            ldsm4(bf[0][jp][0], bf[0][jp][1], bf[0][jp][2], bf[0][jp][3], sb + boff[jp]);

#pragma unroll
        for (int ks = 0; ks < 4; ks++) {
            int cur = ks & 1, nxt = cur ^ 1;
            if (ks < 3) {
#pragma unroll
                for (int ii = 0; ii < 4; ii++)
                    ldsm4(af[nxt][ii][0], af[nxt][ii][1], af[nxt][ii][2], af[nxt][ii][3],
                          sb + aoff[ii] + (ks + 1) * 32);
                rndA(nxt);
#pragma unroll
                for (int jp = 0; jp < 2; jp++)
                    ldsm4(bf[nxt][jp][0], bf[nxt][jp][1], bf[nxt][jp][2], bf[nxt][jp][3],
                          sb + boff[jp] + (ks + 1) * 32);
            }
#pragma unroll
            for (int ii = 0; ii < 4; ii++)
#pragma unroll
                for (int j = 0; j < 4; j++) {
                    unsigned b0 = bf[cur][j >> 1][(j & 1) * 2];
                    unsigned b1 = bf[cur][j >> 1][(j & 1) * 2 + 1];
                    MMA_TF32(acc[ii][j], af[cur][ii], b0, b1);
                }
        }
        __syncthreads();
    }

    int gr = lane >> 2, tg = lane & 3;
#pragma unroll
    for (int i = 0; i < 4; i++) {
#pragma unroll
        for (int j = 0; j < 4; j++) {
            long long r0 = m0 + wm * 64 + i * 16 + gr;
            int c = n0 + wn * 32 + j * 8 + 2 * tg;
            float v0 = acc[i][j][0], v1 = acc[i][j][1];
            float v2 = acc[i][j][2], v3 = acc[i][j][3];
            if (round_out) { v0 = tf32f(v0); v1 = tf32f(v1); v2 = tf32f(v2); v3 = tf32f(v3); }
            *(float2*)(C + r0 * ldc + c)       = make_float2(v0, v1);
            *(float2*)(C + (r0 + 8) * ldc + c) = make_float2(v2, v3);
        }
    }
}

// paired GEMM launch: blocks [0, split) -> set 0, [split, ...) -> set 1 (64-wide tiles)
__global__ void __launch_bounds__(128, 3)
gemm2_kernel(const float* A0, const float* B0, float* C0,
             int K0, int lda0, int ldb0, int ldc0, int ro0, int ra0,
             const float* A1, const float* B1, float* C1,
             int K1, int lda1, int ldb1, int ldc1, int ro1, int ra1,
             int split)
{
    extern __shared__ char smc[];
    int m0 = blockIdx.y * 128;
    int bx = blockIdx.x;
    if (bx < split)
        gemm_body(A0, B0, C0, K0, lda0, ldb0, ldc0, m0, bx * 64, ro0, ra0, smc);
    else
        gemm_body(A1, B1, C1, K1, lda1, ldb1, ldc1, m0, (bx - split) * 64, ro1, ra1, smc);
}

// ---------------- flash attention (R11/R12, proven) ----------------
#define FL_QB 0u
#define FL_KB 100352u
#define FL_V0 150528u
#define FL_V1 185344u
#define FL_SMEM 220160

__global__ void __launch_bounds__(256)
flash_kernel(const float* __restrict__ Qg, const float* __restrict__ Kg,
             const float* __restrict__ Vt, float* __restrict__ O)
{
    extern __shared__ float sm[];
    unsigned sb = (unsigned)__cvta_generic_to_shared(sm);
    int qi = (int)gridDim.x - 1 - (int)blockIdx.x;
    int bh = blockIdx.y;
    int b = bh >> 4, h = bh & 15;
    int q0 = qi * 128;
    int tid = threadIdx.x, lane = tid & 31, wid = tid >> 5;
    int wm = wid;
    int gr = lane >> 2, tg = lane & 3;

    const float* Qp = Qg + ((long long)(b * S_DIM + q0)) * (H_DIM * HEAD) + h * HEAD;
    const float* Kp = Kg + ((long long)(b * S_DIM)) * (H_DIM * HEAD) + h * HEAD;
    const float* Vp = Vt + ((long long)(b * H_DIM + h)) * VD * S_DIM;

    auto loadK = [&](int j) {
        const float* src = Kp + (long long)(j * 64) * (H_DIM * HEAD);
#pragma unroll
        for (int t = 0; t < 12; t++) {
            int idx = tid + t * 256;
            int r = idx / 48, c = idx % 48;
            cp16(sb + FL_KB + r * 784 + c * 16, src + (long long)r * (H_DIM * HEAD) + c * 4);
        }
    };
    auto loadV = [&](int j, int buf) {
        const float* src = Vp + j * 64;
        unsigned dst = sb + (buf ? FL_V1 : FL_V0);
#pragma unroll
        for (int t = 0; t < 8; t++) {
            int idx = tid + t * 256;
            int r = idx >> 4, c = idx & 15;
            cp16(dst + r * 272 + c * 16, src + (long long)r * S_DIM + c * 4);
        }
    };

#pragma unroll
    for (int t = 0; t < 24; t++) {
        int idx = tid + t * 256;
        int r = idx / 48, c = idx % 48;
        cp16(sb + FL_QB + r * 784 + c * 16, Qp + (long long)r * (H_DIM * HEAD) + c * 4);
    }
    loadK(0);
    asm volatile("cp.async.commit_group;");
    loadV(0, 0);
    asm volatile("cp.async.commit_group;");

    unsigned aoffQ, aoffP, boffK[4], boffV[8];
    {
        int R = wm * 16 + (lane & 15);
        aoffQ = (unsigned)(FL_QB + R * 784 + (lane >> 4) * 16);
        aoffP = (unsigned)(R * 272 + (lane >> 4) * 16);
    }
#pragma unroll
    for (int jp = 0; jp < 4; jp++) {
        int R = jp * 16 + ((lane >> 4) & 1) * 8 + (lane & 7);
        boffK[jp] = (unsigned)(FL_KB + R * 784 + ((lane >> 3) & 1) * 16);
    }
#pragma unroll
    for (int jp = 0; jp < 8; jp++) {
        int R = jp * 16 + ((lane >> 4) & 1) * 8 + (lane & 7);
        boffV[jp] = (unsigned)(R * 272 + ((lane >> 3) & 1) * 16);
    }

    float oacc[16][4];
#pragma unroll
    for (int jo = 0; jo < 16; jo++)
#pragma unroll
        for (int r = 0; r < 4; r++) oacc[jo][r] = 0.f;
    float m_[2] = {-1e30f, -1e30f};
    float l_[2] = {0.f, 0.f};

    int jmax = 2 * qi + 1;
    for (int j = 0; j <= jmax; j++) {
        asm volatile("cp.async.wait_group 1;");
        __syncthreads();

        float sacc[8][4];
#pragma unroll
        for (int jj = 0; jj < 8; jj++)
#pragma unroll
            for (int r = 0; r < 4; r++) sacc[jj][r] = 0.f;
        {
            unsigned af[4], bfk[4][4];
#pragma unroll
            for (int ks = 0; ks < 24; ks++) {
                ldsm4(af[0], af[1], af[2], af[3], sb + aoffQ + ks * 32);
#pragma unroll
                for (int jp = 0; jp < 4; jp++)
                    ldsm4(bfk[jp][0], bfk[jp][1], bfk[jp][2], bfk[jp][3], sb + boffK[jp] + ks * 32);
#pragma unroll
                for (int jj = 0; jj < 8; jj++) {
                    unsigned b0 = bfk[jj >> 1][(jj & 1) * 2];
                    unsigned b1 = bfk[jj >> 1][(jj & 1) * 2 + 1];
                    MMA_TF32(sacc[jj], af, b0, b1);
                }
            }
        }
        __syncthreads();
        if (j < jmax) loadK(j + 1);
        asm volatile("cp.async.commit_group;");

        bool mb = (j >= 2 * qi);
        float rm[2] = {-1e30f, -1e30f};
#pragma unroll
        for (int jj = 0; jj < 8; jj++)
#pragma unroll
            for (int k4 = 0; k4 < 4; k4++) {
                float t = sacc[jj][k4] * SCALE_F;
                if (mb) {
                    int col = j * 64 + jj * 8 + 2 * tg + (k4 & 1);
                    int row = q0 + wm * 16 + gr + 8 * (k4 >> 1);
                    if (col > row) t = -1e30f;
                }
                sacc[jj][k4] = t;
                rm[k4 >> 1] = fmaxf(rm[k4 >> 1], t);
            }
#pragma unroll
        for (int s = 0; s < 2; s++) {
            float v = rm[s];
            v = fmaxf(v, __shfl_xor_sync(0xffffffffu, v, 1));
            v = fmaxf(v, __shfl_xor_sync(0xffffffffu, v, 2));
            rm[s] = v;
        }
        float sf[2], rs[2] = {0.f, 0.f};
#pragma unroll
        for (int s = 0; s < 2; s++) {
            float mn = fmaxf(m_[s], rm[s]);
            sf[s] = __expf(m_[s] - mn);
            m_[s] = mn;
        }
#pragma unroll
        for (int jj = 0; jj < 8; jj++)
#pragma unroll
            for (int k4 = 0; k4 < 4; k4++) {
                float p = __expf(sacc[jj][k4] - m_[k4 >> 1]);
                sacc[jj][k4] = p;
                rs[k4 >> 1] += p;
            }
#pragma unroll
        for (int s = 0; s < 2; s++) {
            float v = rs[s];
            v += __shfl_xor_sync(0xffffffffu, v, 1);
            v += __shfl_xor_sync(0xffffffffu, v, 2);
            l_[s] = l_[s] * sf[s] + v;
        }
#pragma unroll
        for (int jo = 0; jo < 16; jo++) {
            oacc[jo][0] *= sf[0]; oacc[jo][1] *= sf[0];
            oacc[jo][2] *= sf[1]; oacc[jo][3] *= sf[1];
        }

        unsigned pB = sb + (((j + 1) & 1) ? FL_V1 : FL_V0);
#pragma unroll
        for (int jj = 0; jj < 8; jj++) {
            int colb = (jj * 8 + 2 * tg) * 4;
            int r0 = wm * 16 + gr;
            float2 v0 = make_float2(tf32f(sacc[jj][0]), tf32f(sacc[jj][1]));
            float2 v1 = make_float2(tf32f(sacc[jj][2]), tf32f(sacc[jj][3]));
            asm volatile("st.shared.v2.f32 [%0], {%1, %2};" :: "r"(pB + r0 * 272 + colb), "f"(v0.x), "f"(v0.y));
            asm volatile("st.shared.v2.f32 [%0], {%1, %2};" :: "r"(pB + (r0 + 8) * 272 + colb), "f"(v1.x), "f"(v1.y));
        }
        asm volatile("cp.async.wait_group 1;");
        __syncthreads();

        {
            unsigned vB = sb + ((j & 1) ? FL_V1 : FL_V0);
            unsigned afp[4], bfv[8][4];
#pragma unroll
            for (int ks = 0; ks < 8; ks++) {
                ldsm4(afp[0], afp[1], afp[2], afp[3], pB + aoffP + ks * 32);
#pragma unroll
                for (int jp = 0; jp < 8; jp++)
                    ldsm4(bfv[jp][0], bfv[jp][1], bfv[jp][2], bfv[jp][3], vB + boffV[jp] + ks * 32);
#pragma unroll
                for (int jo = 0; jo < 16; jo++) {
                    unsigned b0 = bfv[jo >> 1][(jo & 1) * 2];
                    unsigned b1 = bfv[jo >> 1][(jo & 1) * 2 + 1];
                    MMA_TF32(oacc[jo], afp, b0, b1);
                }
            }
        }
        __syncthreads();
        if (j < jmax) loadV(j + 1, (j + 1) & 1);
        asm volatile("cp.async.commit_group;");
    }

    float il[2] = {1.0f / l_[0], 1.0f / l_[1]};
#pragma unroll
    for (int jo = 0; jo < 16; jo++) {
        long long r0 = (long long)(b * S_DIM + q0 + wm * 16 + gr);
        int c = jo * 8 + 2 * tg;
        float* d0 = O + r0 * (H_DIM * VD) + h * VD + c;
        float* d1 = d0 + 8LL * (H_DIM * VD);
        *(float2*)d0 = make_float2(tf32f(oacc[jo][0] * il[0]),
                                   tf32f(oacc[jo][1] * il[0]));
        *(float2*)d1 = make_float2(tf32f(oacc[jo][2] * il[1]),
                                   tf32f(oacc[jo][3] * il[1]));
    }
}

// ---------------- pre-pass: 5 weight transposes (no hidden copy) ----------------
__global__ void __launch_bounds__(256)
prep_kernel(const float* __restrict__ w_q_a, const float* __restrict__ w_q_b,
            const float* __restrict__ w_kv_a, const float* __restrict__ w_kv_b,
            const float* __restrict__ w_o,
            float* __restrict__ wqaT, float* __restrict__ wqbT,
            float* __restrict__ wkvaT, float* __restrict__ wkvbT,
            float* __restrict__ woT)
{
    int tile = blockIdx.x;
    int tid = threadIdx.x;

    const float* in; float* out; int K, N, idx;
    if (tile < 3072)       { in = w_q_a;  out = wqaT;  K = 2048; N = 1536; idx = tile; }
    else if (tile < 7680)  { in = w_q_b;  out = wqbT;  K = 1536; N = 3072; idx = tile - 3072; }
    else if (tile < 8832)  { in = w_kv_a; out = wkvaT; K = 2048; N = 576;  idx = tile - 7680; }
    else if (tile < 10880) { in = w_kv_b; out = wkvbT; K = 512;  N = 4096; idx = tile - 8832; }
    else                   { in = w_o;    out = woT;   K = 2048; N = 2048; idx = tile - 10880; }

    int nx = N >> 5;
    int n0 = (idx % nx) * 32;
    int k0 = (idx / nx) * 32;

    __shared__ float t[32][33];
    int x = tid & 31, y = tid >> 5;
#pragma unroll
    for (int i = y; i < 32; i += 8)
        t[i][x] = in[(long long)(k0 + i) * N + n0 + x];
    __syncthreads();
#pragma unroll
    for (int i = y; i < 32; i += 8)
        out[(long long)(n0 + i) * K + k0 + x] = tf32f(t[x][i]);
}

// ---------------- merged post-pass: rope_q + build_key + vtrans ----------------
// blocks [0,4096): rope on q (one t each); [4096,8192): build key (one t each);
// [8192,16384): V transpose tiles. 256 threads everywhere.
__global__ void __launch_bounds__(256)
post_kernel(float* __restrict__ q, const float* __restrict__ kv,
            const float* __restrict__ ckv,
            const float* __restrict__ cosp, const float* __restrict__ sinp,
            float* __restrict__ key, float* __restrict__ vT)
{
    int bx = blockIdx.x;
    int tid = threadIdx.x;

    if (bx < T_DIM) {                       // rope q (in place, rounded)
        int t = bx;
#pragma unroll
        for (int half = 0; half < 2; half++) {
            int it = tid + half * 256;      // 0..511
            int h = it >> 5, i = it & 31;
            float* pe = q + ((long long)t * H_DIM + h) * HEAD + NOPE;
            float e = pe[2 * i], o = pe[2 * i + 1];
            float c = cosp[t * 32 + i], s = sinp[t * 32 + i];
            __syncwarp();
            pe[i]      = tf32f(e * c - o * s);
            pe[32 + i] = tf32f(o * c + e * s);
        }
        return;
    }
    if (bx < 2 * T_DIM) {                   // build key (rounded)
        int t = bx - T_DIM;
        long long base = (long long)t * (H_DIM * HEAD);
        const float* kvr = kv + (long long)t * (H_DIM * 256);
        for (int idx = tid; idx < H_DIM * NOPE; idx += 256) {
            int h = idx >> 7, d = idx & 127;
            key[base + h * HEAD + d] = tf32f(kvr[h * 256 + d]);
        }
        // rope part: 16 heads x 32 pairs = 512 items
        const float* pe = ckv + (long long)t * (KV_RANK + ROPE) + KV_RANK;
#pragma unroll
        for (int half = 0; half < 2; half++) {
            int it = tid + half * 256;
            int h = it >> 5, i = it & 31;
            float e = pe[2 * i], o = pe[2 * i + 1];
            float c = cosp[t * 32 + i], s = sinp[t * 32 + i];
            key[base + h * HEAD + NOPE + i]      = tf32f(e * c - o * s);
            key[base + h * HEAD + NOPE + 32 + i] = tf32f(o * c + e * s);
        }
        return;
    }
    // vtrans: 8192 tiles -> (sx 64, dy 4, z 32)
    int vb = bx - 2 * T_DIM;
    int sx = vb & 63, dy = (vb >> 6) & 3, z = vb >> 8;
    int b = z >> 4, h = z & 15;
    int s0 = sx * 32, d0 = dy * 32;
    __shared__ float t[32][33];
    int x = tid & 31, y = tid >> 5;
#pragma unroll
    for (int i = y; i < 32; i += 8)
        t[i][x] = kv[(long long)(b * S_DIM + s0 + i) * (H_DIM * 256) + h * 256 + 128 + d0 + x];
    __syncthreads();
#pragma unroll
    for (int i = y; i < 32; i += 8)
        vT[((long long)(b * H_DIM + h) * VD + d0 + i) * S_DIM + s0 + x] = tf32f(t[x][i]);
}

// ---------------- merged rmsnorm (qa rows then ckv rows) ----------------
__global__ void rmsnorm2_kernel(const float* __restrict__ x0, const float* __restrict__ w0,
                                float* __restrict__ y0,
                                const float* __restrict__ x1, const float* __restrict__ w1,
                                float* __restrict__ y1)
{
    const float4 *xr, *wr; float4* yr; int N;
    long long row;
    if (blockIdx.x < T_DIM) {
        row = blockIdx.x;
        N = Q_RANK;
        xr = (const float4*)x0 + row * (Q_RANK >> 2); wr = (const float4*)w0;
        yr = (float4*)y0 + row * (Q_RANK >> 2);
    } else {
        row = blockIdx.x - T_DIM;
        N = KV_RANK;
        xr = (const float4*)x1 + row * ((KV_RANK + ROPE) >> 2); wr = (const float4*)w1;
        yr = (float4*)y1 + row * (KV_RANK >> 2);
    }
    int tid = threadIdx.x;
    int nv = N >> 2;

    float ss = 0.f;
    for (int i = tid; i < nv; i += 256) {
        float4 v = xr[i];
        ss += v.x * v.x + v.y * v.y + v.z * v.z + v.w * v.w;
    }
    __shared__ float red[256];
    red[tid] = ss; __syncthreads();
#pragma unroll
    for (int s = 128; s > 0; s >>= 1) {
        if (tid < s) red[tid] += red[tid + s];
        __syncthreads();
    }
    float sc = rsqrtf(red[0] / (float)N + EPS_F);
    for (int i = tid; i < nv; i += 256) {
        float4 v = xr[i], ww = wr[i];
        v.x = tf32f(v.x * sc * ww.x); v.y = tf32f(v.y * sc * ww.y);
        v.z = tf32f(v.z * sc * ww.z); v.w = tf32f(v.w * sc * ww.w);
        yr[i] = v;
    }
}

// ---------------- launch ----------------
extern "C" void kernel_launch(void* const* d_in, const int* in_sizes, int n_in,
                              void* d_out, int out_size)
{
    const float* hidden   = (const float*)d_in[0];
    const float* cosp     = (const float*)d_in[1];
    const float* sinp     = (const float*)d_in[2];
    const float* w_q_a    = (const float*)d_in[3];
    const float* q_a_ln_w = (const float*)d_in[4];
    const float* w_q_b    = (const float*)d_in[5];
    const float* w_kv_a   = (const float*)d_in[6];
    const float* kv_a_ln_w= (const float*)d_in[7];
    const float* w_kv_b   = (const float*)d_in[8];
    const float* w_o      = (const float*)d_in[9];
    float* out = (float*)d_out;

    float *p_qa, *p_qan, *p_q, *p_ckv, *p_ckvn, *p_kv, *p_key, *p_attn;
    float *p_wqaT, *p_wqbT, *p_wkvaT, *p_wkvbT, *p_woT, *p_vT;
    cudaGetSymbolAddress((void**)&p_qa,     g_qa);
    cudaGetSymbolAddress((void**)&p_qan,    g_qan);
    cudaGetSymbolAddress((void**)&p_q,      g_q);
    cudaGetSymbolAddress((void**)&p_ckv,    g_ckv);
    cudaGetSymbolAddress((void**)&p_ckvn,   g_ckvn);
    cudaGetSymbolAddress((void**)&p_kv,     g_kv);
    cudaGetSymbolAddress((void**)&p_key,    g_key);
    cudaGetSymbolAddress((void**)&p_attn,   g_attn);
    cudaGetSymbolAddress((void**)&p_wqaT,   g_wqaT);
    cudaGetSymbolAddress((void**)&p_wqbT,   g_wqbT);
    cudaGetSymbolAddress((void**)&p_wkvaT,  g_wkvaT);
    cudaGetSymbolAddress((void**)&p_wkvbT,  g_wkvbT);
    cudaGetSymbolAddress((void**)&p_woT,    g_woT);
    cudaGetSymbolAddress((void**)&p_vT,     g_vT);

    const int SMEM = 2 * STG_B;   // 55296
    cudaFuncSetAttribute(gemm2_kernel, cudaFuncAttributeMaxDynamicSharedMemorySize, SMEM);
    cudaFuncSetAttribute(flash_kernel, cudaFuncAttributeMaxDynamicSharedMemorySize, FL_SMEM);

    // 1. pre-pass: weight transposes only
    prep_kernel<<<14976, 256>>>(w_q_a, w_q_b, w_kv_a, w_kv_b, w_o,
                                p_wqaT, p_wqbT, p_wkvaT, p_wkvbT, p_woT);

    // 2. G1: qa = hidden@wqaT (24 tiles) || ckv = hidden@wkvaT (9 tiles); A rounded in-kernel
    gemm2_kernel<<<dim3(33, T_DIM/128, 1), 128, SMEM>>>(
        hidden, p_wqaT,  p_qa,  D_DIM, D_DIM, D_DIM, Q_RANK, 0, 1,
        hidden, p_wkvaT, p_ckv, D_DIM, D_DIM, D_DIM, KV_RANK+ROPE, 0, 1,
        24);

    // 3. merged rmsnorm (qa -> qan, ckv[:512] -> ckvn)
    rmsnorm2_kernel<<<2 * T_DIM, 256>>>(p_qa, q_a_ln_w, p_qan,
                                        p_ckv, kv_a_ln_w, p_ckvn);

    // 4. G2: q = qan@wqbT (48 tiles, rounded out) || kv = ckvn@wkvbT (64 tiles)
    gemm2_kernel<<<dim3(112, T_DIM/128, 1), 128, SMEM>>>(
        p_qan,  p_wqbT,  p_q,  Q_RANK,  Q_RANK,  Q_RANK,  H_DIM*HEAD, 1, 0,
        p_ckvn, p_wkvbT, p_kv, KV_RANK, KV_RANK, KV_RANK, H_DIM*256,  0, 0,
        48);

    // 5. merged post-pass: rope q + build key + V transpose
    post_kernel<<<4 * T_DIM, 256>>>(p_q, p_kv, p_ckv, cosp, sinp, p_key, p_vT);

    // 6. fused flash attention -> g_attn
    flash_kernel<<<dim3(S_DIM/128, B_DIM*H_DIM), 256, FL_SMEM>>>(p_q, p_key, p_vT, p_attn);

    // 7. out = attn @ woT (32 tiles)
    gemm2_kernel<<<dim3(32, T_DIM/128, 1), 128, SMEM>>>(
        p_attn, p_woT, out, H_DIM*VD, H_DIM*VD, H_DIM*VD, D_DIM, 0, 0,
        p_attn, p_woT, out, H_DIM*VD, H_DIM*VD, H_DIM*VD, D_DIM, 0, 0,
        32);
}

// round 15
// speedup vs baseline: 1.0576x; 1.0576x over previous
#include <cuda_runtime.h>
#include <cuda_bf16.h>
#include <math.h>

// ---------------- problem constants ----------------
#define T_DIM 4096
#define D_DIM 2048
#define H_DIM 16
#define NOPE 128
#define ROPE 64
#define VD 128
#define KV_RANK 512
#define HEAD 192               // NOPE + ROPE
#define Q_RANK 1536
#define B_DIM 2
#define S_DIM 2048
#define SCALE_F 0.072168783648703220563f   // 192^-0.5
#define EPS_F 1e-6f

// ---------------- scratch ----------------
__device__ float g_qa  [(long long)T_DIM * Q_RANK];
__device__ float g_qan [(long long)T_DIM * Q_RANK];
__device__ float g_q   [(long long)T_DIM * H_DIM * HEAD];
__device__ float g_ckv [(long long)T_DIM * (KV_RANK + ROPE)];
__device__ float g_ckvn[(long long)T_DIM * KV_RANK];
__device__ float g_kv  [(long long)T_DIM * H_DIM * (NOPE + VD)];
__device__ float g_key [(long long)T_DIM * H_DIM * HEAD];
__device__ float g_attn[(long long)T_DIM * H_DIM * VD];
// transposed (tf32-rounded) weights / V
__device__ float g_wqaT [(long long)Q_RANK * D_DIM];
__device__ float g_wqbT [(long long)H_DIM * HEAD * Q_RANK];
__device__ float g_wkvaT[(long long)(KV_RANK + ROPE) * D_DIM];
__device__ float g_wkvbT[(long long)H_DIM * (NOPE + VD) * KV_RANK];
__device__ float g_woT  [(long long)D_DIM * H_DIM * VD];
__device__ float g_vT   [(long long)B_DIM * H_DIM * VD * S_DIM];

__device__ __forceinline__ float tf32f(float f) {
    unsigned u; asm("cvt.rna.tf32.f32 %0, %1;" : "=r"(u) : "f"(f));
    return __uint_as_float(u);
}
__device__ __forceinline__ unsigned tf32r(unsigned u) {
    unsigned o; asm("cvt.rna.tf32.f32 %0, %1;" : "=r"(o) : "f"(__uint_as_float(u)));
    return o;
}
__device__ __forceinline__ void cp16(unsigned dst, const void* src) {
    asm volatile("cp.async.cg.shared.global [%0], [%1], 16;\n"
                 :: "r"(dst), "l"(src));
}
__device__ __forceinline__ void ldsm4(unsigned& r0, unsigned& r1, unsigned& r2, unsigned& r3,
                                      unsigned addr) {
    asm volatile("ldmatrix.sync.aligned.m8n8.x4.shared.b16 {%0,%1,%2,%3}, [%4];"
                 : "=r"(r0), "=r"(r1), "=r"(r2), "=r"(r3) : "r"(addr));
}
#define MMA_TF32(acc, a, b0, b1) \
    asm volatile("mma.sync.aligned.m16n8k8.row.col.f32.tf32.tf32.f32 " \
                 "{%0,%1,%2,%3},{%4,%5,%6,%7},{%8,%9},{%0,%1,%2,%3};" \
                 : "+f"(acc[0]), "+f"(acc[1]), "+f"(acc[2]), "+f"(acc[3]) \
                 : "r"(a[0]), "r"(a[1]), "r"(a[2]), "r"(a[3]), "r"(b0), "r"(b1))

// ---------------- NT tf32 GEMM body (R12 proven): 128x64x32, 4 warps, 2 stages, frag-db -----
// RA: round A fragments to tf32 after ldmatrix (compile-time; zero cost when false)
#define STG_B 27648
#define BOFF_B 18432

template<bool RA>
__device__ __forceinline__ void gemm_body(
    const float* __restrict__ A, const float* __restrict__ B, float* __restrict__ C,
    int K, int lda, int ldb, int ldc, int m0, int n0, int round_out, char* smc)
{
    float* sm = (float*)smc;
    int nIter = K >> 5;
    int tid  = threadIdx.x;
    int lane = tid & 31;
    int wid  = tid >> 5;
    int wm   = wid & 1;
    int wn   = wid >> 1;

    unsigned sbase = (unsigned)__cvta_generic_to_shared(sm);
    int lrow = tid >> 3;
    int lc   = tid & 7;

    auto issue = [&](int itk) {
        int k0 = itk << 5;
        unsigned sb = sbase + (unsigned)(itk & 1) * STG_B;
        const float* Ap = A + (long long)(m0 + lrow) * lda + k0 + lc * 4;
        unsigned ad = sb + lrow * 144 + lc * 16;
#pragma unroll
        for (int it = 0; it < 8; it++)
            cp16(ad + it * (16 * 144), Ap + (long long)(it * 16) * lda);
        const float* Bp = B + (long long)(n0 + lrow) * ldb + k0 + lc * 4;
        unsigned bd = sb + BOFF_B + lrow * 144 + lc * 16;
#pragma unroll
        for (int it = 0; it < 4; it++)
            cp16(bd + it * (16 * 144), Bp + (long long)(it * 16) * ldb);
        asm volatile("cp.async.commit_group;");
    };

    issue(0);

    unsigned aoff[4], boff[2];
#pragma unroll
    for (int i = 0; i < 4; i++) {
        int R = wm * 64 + i * 16 + (lane & 15);
        aoff[i] = (unsigned)(R * 144 + (lane >> 4) * 16);
    }
#pragma unroll
    for (int jp = 0; jp < 2; jp++) {
        int R = wn * 32 + jp * 16 + ((lane >> 4) & 1) * 8 + (lane & 7);
        boff[jp] = (unsigned)(BOFF_B + R * 144 + ((lane >> 3) & 1) * 16);
    }

    float acc[4][4][4];
#pragma unroll
    for (int i = 0; i < 4; i++)
#pragma unroll
        for (int j = 0; j < 4; j++)
#pragma unroll
            for (int r = 0; r < 4; r++) acc[i][j][r] = 0.f;

    unsigned af[2][4][4], bf[2][2][4];

    for (int i = 0; i < nIter; i++) {
        if (i + 1 < nIter) {
            issue(i + 1);
            asm volatile("cp.async.wait_group 1;");
        } else {
            asm volatile("cp.async.wait_group 0;");
        }
        __syncthreads();

        unsigned sb = sbase + (unsigned)(i & 1) * STG_B;
#pragma unroll
        for (int ii = 0; ii < 4; ii++)
            ldsm4(af[0][ii][0], af[0][ii][1], af[0][ii][2], af[0][ii][3], sb + aoff[ii]);
        if (RA) {
#pragma unroll
            for (int ii = 0; ii < 4; ii++)
#pragma unroll
                for (int r = 0; r < 4; r++) af[0][ii][r] = tf32r(af[0][ii][r]);
        }
#pragma unroll
        for (int jp = 0; jp < 2; jp++)
            ldsm4(bf[0][jp][0], bf[0][jp][1], bf[0][jp][2], bf[0][jp][3], sb + boff[jp]);

#pragma unroll
        for (int ks = 0; ks < 4; ks++) {
            int cur = ks & 1, nxt = cur ^ 1;
            if (ks < 3) {
#pragma unroll
                for (int ii = 0; ii < 4; ii++)
                    ldsm4(af[nxt][ii][0], af[nxt][ii][1], af[nxt][ii][2], af[nxt][ii][3],
                          sb + aoff[ii] + (ks + 1) * 32);
                if (RA) {
#pragma unroll
                    for (int ii = 0; ii < 4; ii++)
#pragma unroll
                        for (int r = 0; r < 4; r++) af[nxt][ii][r] = tf32r(af[nxt][ii][r]);
                }
#pragma unroll
                for (int jp = 0; jp < 2; jp++)
                    ldsm4(bf[nxt][jp][0], bf[nxt][jp][1], bf[nxt][jp][2], bf[nxt][jp][3],
                          sb + boff[jp] + (ks + 1) * 32);
            }
#pragma unroll
            for (int ii = 0; ii < 4; ii++)
#pragma unroll
                for (int j = 0; j < 4; j++) {
                    unsigned b0 = bf[cur][j >> 1][(j & 1) * 2];
                    unsigned b1 = bf[cur][j >> 1][(j & 1) * 2 + 1];
                    MMA_TF32(acc[ii][j], af[cur][ii], b0, b1);
                }
        }
        __syncthreads();
    }

    int gr = lane >> 2, tg = lane & 3;
#pragma unroll
    for (int i = 0; i < 4; i++) {
#pragma unroll
        for (int j = 0; j < 4; j++) {
            long long r0 = m0 + wm * 64 + i * 16 + gr;
            int c = n0 + wn * 32 + j * 8 + 2 * tg;
            float v0 = acc[i][j][0], v1 = acc[i][j][1];
            float v2 = acc[i][j][2], v3 = acc[i][j][3];
            if (round_out) { v0 = tf32f(v0); v1 = tf32f(v1); v2 = tf32f(v2); v3 = tf32f(v3); }
            *(float2*)(C + r0 * ldc + c)       = make_float2(v0, v1);
            *(float2*)(C + (r0 + 8) * ldc + c) = make_float2(v2, v3);
        }
    }
}

// paired GEMM launch: blocks [0, split) -> set 0, [split, ...) -> set 1 (64-wide tiles)
template<bool RA0, bool RA1>
__global__ void __launch_bounds__(128, 3)
gemm2_kernel(const float* A0, const float* B0, float* C0,
             int K0, int lda0, int ldb0, int ldc0, int ro0,
             const float* A1, const float* B1, float* C1,
             int K1, int lda1, int ldb1, int ldc1, int ro1,
             int split)
{
    extern __shared__ char smc[];
    int m0 = blockIdx.y * 128;
    int bx = blockIdx.x;
    if (bx < split)
        gemm_body<RA0>(A0, B0, C0, K0, lda0, ldb0, ldc0, m0, bx * 64, ro0, smc);
    else
        gemm_body<RA1>(A1, B1, C1, K1, lda1, ldb1, ldc1, m0, (bx - split) * 64, ro1, smc);
}

// ---------------- flash attention (R11/R12, proven) ----------------
#define FL_QB 0u
#define FL_KB 100352u
#define FL_V0 150528u
#define FL_V1 185344u
#define FL_SMEM 220160

__global__ void __launch_bounds__(256)
flash_kernel(const float* __restrict__ Qg, const float* __restrict__ Kg,
             const float* __restrict__ Vt, float* __restrict__ O)
{
    extern __shared__ float sm[];
    unsigned sb = (unsigned)__cvta_generic_to_shared(sm);
    int qi = (int)gridDim.x - 1 - (int)blockIdx.x;
    int bh = blockIdx.y;
    int b = bh >> 4, h = bh & 15;
    int q0 = qi * 128;
    int tid = threadIdx.x, lane = tid & 31, wid = tid >> 5;
    int wm = wid;
    int gr = lane >> 2, tg = lane & 3;

    const float* Qp = Qg + ((long long)(b * S_DIM + q0)) * (H_DIM * HEAD) + h * HEAD;
    const float* Kp = Kg + ((long long)(b * S_DIM)) * (H_DIM * HEAD) + h * HEAD;
    const float* Vp = Vt + ((long long)(b * H_DIM + h)) * VD * S_DIM;

    auto loadK = [&](int j) {
        const float* src = Kp + (long long)(j * 64) * (H_DIM * HEAD);
#pragma unroll
        for (int t = 0; t < 12; t++) {
            int idx = tid + t * 256;
            int r = idx / 48, c = idx % 48;
            cp16(sb + FL_KB + r * 784 + c * 16, src + (long long)r * (H_DIM * HEAD) + c * 4);
        }
    };
    auto loadV = [&](int j, int buf) {
        const float* src = Vp + j * 64;
        unsigned dst = sb + (buf ? FL_V1 : FL_V0);
#pragma unroll
        for (int t = 0; t < 8; t++) {
            int idx = tid + t * 256;
            int r = idx >> 4, c = idx & 15;
            cp16(dst + r * 272 + c * 16, src + (long long)r * S_DIM + c * 4);
        }
    };

#pragma unroll
    for (int t = 0; t < 24; t++) {
        int idx = tid + t * 256;
        int r = idx / 48, c = idx % 48;
        cp16(sb + FL_QB + r * 784 + c * 16, Qp + (long long)r * (H_DIM * HEAD) + c * 4);
    }
    loadK(0);
    asm volatile("cp.async.commit_group;");
    loadV(0, 0);
    asm volatile("cp.async.commit_group;");

    unsigned aoffQ, aoffP, boffK[4], boffV[8];
    {
        int R = wm * 16 + (lane & 15);
        aoffQ = (unsigned)(FL_QB + R * 784 + (lane >> 4) * 16);
        aoffP = (unsigned)(R * 272 + (lane >> 4) * 16);
    }
#pragma unroll
    for (int jp = 0; jp < 4; jp++) {
        int R = jp * 16 + ((lane >> 4) & 1) * 8 + (lane & 7);
        boffK[jp] = (unsigned)(FL_KB + R * 784 + ((lane >> 3) & 1) * 16);
    }
#pragma unroll
    for (int jp = 0; jp < 8; jp++) {
        int R = jp * 16 + ((lane >> 4) & 1) * 8 + (lane & 7);
        boffV[jp] = (unsigned)(R * 272 + ((lane >> 3) & 1) * 16);
    }

    float oacc[16][4];
#pragma unroll
    for (int jo = 0; jo < 16; jo++)
#pragma unroll
        for (int r = 0; r < 4; r++) oacc[jo][r] = 0.f;
    float m_[2] = {-1e30f, -1e30f};
    float l_[2] = {0.f, 0.f};

    int jmax = 2 * qi + 1;
    for (int j = 0; j <= jmax; j++) {
        asm volatile("cp.async.wait_group 1;");
        __syncthreads();

        float sacc[8][4];
#pragma unroll
        for (int jj = 0; jj < 8; jj++)
#pragma unroll
            for (int r = 0; r < 4; r++) sacc[jj][r] = 0.f;
        {
            unsigned af[4], bfk[4][4];
#pragma unroll
            for (int ks = 0; ks < 24; ks++) {
                ldsm4(af[0], af[1], af[2], af[3], sb + aoffQ + ks * 32);
#pragma unroll
                for (int jp = 0; jp < 4; jp++)
                    ldsm4(bfk[jp][0], bfk[jp][1], bfk[jp][2], bfk[jp][3], sb + boffK[jp] + ks * 32);
#pragma unroll
                for (int jj = 0; jj < 8; jj++) {
                    unsigned b0 = bfk[jj >> 1][(jj & 1) * 2];
                    unsigned b1 = bfk[jj >> 1][(jj & 1) * 2 + 1];
                    MMA_TF32(sacc[jj], af, b0, b1);
                }
            }
        }
        __syncthreads();
        if (j < jmax) loadK(j + 1);
        asm volatile("cp.async.commit_group;");

        bool mb = (j >= 2 * qi);
        float rm[2] = {-1e30f, -1e30f};
#pragma unroll
        for (int jj = 0; jj < 8; jj++)
#pragma unroll
            for (int k4 = 0; k4 < 4; k4++) {
                float t = sacc[jj][k4] * SCALE_F;
                if (mb) {
                    int col = j * 64 + jj * 8 + 2 * tg + (k4 & 1);
                    int row = q0 + wm * 16 + gr + 8 * (k4 >> 1);
                    if (col > row) t = -1e30f;
                }
                sacc[jj][k4] = t;
                rm[k4 >> 1] = fmaxf(rm[k4 >> 1], t);
            }
#pragma unroll
        for (int s = 0; s < 2; s++) {
            float v = rm[s];
            v = fmaxf(v, __shfl_xor_sync(0xffffffffu, v, 1));
            v = fmaxf(v, __shfl_xor_sync(0xffffffffu, v, 2));
            rm[s] = v;
        }
        float sf[2], rs[2] = {0.f, 0.f};
#pragma unroll
        for (int s = 0; s < 2; s++) {
            float mn = fmaxf(m_[s], rm[s]);
            sf[s] = __expf(m_[s] - mn);
            m_[s] = mn;
        }
#pragma unroll
        for (int jj = 0; jj < 8; jj++)
#pragma unroll
            for (int k4 = 0; k4 < 4; k4++) {
                float p = __expf(sacc[jj][k4] - m_[k4 >> 1]);
                sacc[jj][k4] = p;
                rs[k4 >> 1] += p;
            }
#pragma unroll
        for (int s = 0; s < 2; s++) {
            float v = rs[s];
            v += __shfl_xor_sync(0xffffffffu, v, 1);
            v += __shfl_xor_sync(0xffffffffu, v, 2);
            l_[s] = l_[s] * sf[s] + v;
        }
#pragma unroll
        for (int jo = 0; jo < 16; jo++) {
            oacc[jo][0] *= sf[0]; oacc[jo][1] *= sf[0];
            oacc[jo][2] *= sf[1]; oacc[jo][3] *= sf[1];
        }

        unsigned pB = sb + (((j + 1) & 1) ? FL_V1 : FL_V0);
#pragma unroll
        for (int jj = 0; jj < 8; jj++) {
            int colb = (jj * 8 + 2 * tg) * 4;
            int r0 = wm * 16 + gr;
            float2 v0 = make_float2(tf32f(sacc[jj][0]), tf32f(sacc[jj][1]));
            float2 v1 = make_float2(tf32f(sacc[jj][2]), tf32f(sacc[jj][3]));
            asm volatile("st.shared.v2.f32 [%0], {%1, %2};" :: "r"(pB + r0 * 272 + colb), "f"(v0.x), "f"(v0.y));
            asm volatile("st.shared.v2.f32 [%0], {%1, %2};" :: "r"(pB + (r0 + 8) * 272 + colb), "f"(v1.x), "f"(v1.y));
        }
        asm volatile("cp.async.wait_group 1;");
        __syncthreads();

        {
            unsigned vB = sb + ((j & 1) ? FL_V1 : FL_V0);
            unsigned afp[4], bfv[8][4];
#pragma unroll
            for (int ks = 0; ks < 8; ks++) {
                ldsm4(afp[0], afp[1], afp[2], afp[3], pB + aoffP + ks * 32);
#pragma unroll
                for (int jp = 0; jp < 8; jp++)
                    ldsm4(bfv[jp][0], bfv[jp][1], bfv[jp][2], bfv[jp][3], vB + boffV[jp] + ks * 32);
#pragma unroll
                for (int jo = 0; jo < 16; jo++) {
                    unsigned b0 = bfv[jo >> 1][(jo & 1) * 2];
                    unsigned b1 = bfv[jo >> 1][(jo & 1) * 2 + 1];
                    MMA_TF32(oacc[jo], afp, b0, b1);
                }
            }
        }
        __syncthreads();
        if (j < jmax) loadV(j + 1, (j + 1) & 1);
        asm volatile("cp.async.commit_group;");
    }

    float il[2] = {1.0f / l_[0], 1.0f / l_[1]};
#pragma unroll
    for (int jo = 0; jo < 16; jo++) {
        long long r0 = (long long)(b * S_DIM + q0 + wm * 16 + gr);
        int c = jo * 8 + 2 * tg;
        float* d0 = O + r0 * (H_DIM * VD) + h * VD + c;
        float* d1 = d0 + 8LL * (H_DIM * VD);
        *(float2*)d0 = make_float2(tf32f(oacc[jo][0] * il[0]),
                                   tf32f(oacc[jo][1] * il[0]));
        *(float2*)d1 = make_float2(tf32f(oacc[jo][2] * il[1]),
                                   tf32f(oacc[jo][3] * il[1]));
    }
}

// ---------------- pre-pass: 5 weight transposes (no hidden copy) ----------------
__global__ void __launch_bounds__(256)
prep_kernel(const float* __restrict__ w_q_a, const float* __restrict__ w_q_b,
            const float* __restrict__ w_kv_a, const float* __restrict__ w_kv_b,
            const float* __restrict__ w_o,
            float* __restrict__ wqaT, float* __restrict__ wqbT,
            float* __restrict__ wkvaT, float* __restrict__ wkvbT,
            float* __restrict__ woT)
{
    int tile = blockIdx.x;
    int tid = threadIdx.x;

    const float* in; float* out; int K, N, idx;
    if (tile < 3072)       { in = w_q_a;  out = wqaT;  K = 2048; N = 1536; idx = tile; }
    else if (tile < 7680)  { in = w_q_b;  out = wqbT;  K = 1536; N = 3072; idx = tile - 3072; }
    else if (tile < 8832)  { in = w_kv_a; out = wkvaT; K = 2048; N = 576;  idx = tile - 7680; }
    else if (tile < 10880) { in = w_kv_b; out = wkvbT; K = 512;  N = 4096; idx = tile - 8832; }
    else                   { in = w_o;    out = woT;   K = 2048; N = 2048; idx = tile - 10880; }

    int nx = N >> 5;
    int n0 = (idx % nx) * 32;
    int k0 = (idx / nx) * 32;

    __shared__ float t[32][33];
    int x = tid & 31, y = tid >> 5;
#pragma unroll
    for (int i = y; i < 32; i += 8)
        t[i][x] = in[(long long)(k0 + i) * N + n0 + x];
    __syncthreads();
#pragma unroll
    for (int i = y; i < 32; i += 8)
        out[(long long)(n0 + i) * K + k0 + x] = tf32f(t[x][i]);
}

// ---------------- merged post-pass: rope_q + build_key + vtrans ----------------
__global__ void __launch_bounds__(256)
post_kernel(float* __restrict__ q, const float* __restrict__ kv,
            const float* __restrict__ ckv,
            const float* __restrict__ cosp, const float* __restrict__ sinp,
            float* __restrict__ key, float* __restrict__ vT)
{
    int bx = blockIdx.x;
    int tid = threadIdx.x;

    if (bx < T_DIM) {                       // rope q (in place, rounded)
        int t = bx;
#pragma unroll
        for (int half = 0; half < 2; half++) {
            int it = tid + half * 256;      // 0..511
            int h = it >> 5, i = it & 31;
            float* pe = q + ((long long)t * H_DIM + h) * HEAD + NOPE;
            float e = pe[2 * i], o = pe[2 * i + 1];
            float c = cosp[t * 32 + i], s = sinp[t * 32 + i];
            __syncwarp();
            pe[i]      = tf32f(e * c - o * s);
            pe[32 + i] = tf32f(o * c + e * s);
        }
        return;
    }
    if (bx < 2 * T_DIM) {                   // build key (rounded)
        int t = bx - T_DIM;
        long long base = (long long)t * (H_DIM * HEAD);
        const float* kvr = kv + (long long)t * (H_DIM * 256);
        for (int idx = tid; idx < H_DIM * NOPE; idx += 256) {
            int h = idx >> 7, d = idx & 127;
            key[base + h * HEAD + d] = tf32f(kvr[h * 256 + d]);
        }
        const float* pe = ckv + (long long)t * (KV_RANK + ROPE) + KV_RANK;
#pragma unroll
        for (int half = 0; half < 2; half++) {
            int it = tid + half * 256;
            int h = it >> 5, i = it & 31;
            float e = pe[2 * i], o = pe[2 * i + 1];
            float c = cosp[t * 32 + i], s = sinp[t * 32 + i];
            key[base + h * HEAD + NOPE + i]      = tf32f(e * c - o * s);
            key[base + h * HEAD + NOPE + 32 + i] = tf32f(o * c + e * s);
        }
        return;
    }
    // vtrans: 8192 tiles -> (sx 64, dy 4, z 32)
    int vb = bx - 2 * T_DIM;
    int sx = vb & 63, dy = (vb >> 6) & 3, z = vb >> 8;
    int b = z >> 4, h = z & 15;
    int s0 = sx * 32, d0 = dy * 32;
    __shared__ float t[32][33];
    int x = tid & 31, y = tid >> 5;
#pragma unroll
    for (int i = y; i < 32; i += 8)
        t[i][x] = kv[(long long)(b * S_DIM + s0 + i) * (H_DIM * 256) + h * 256 + 128 + d0 + x];
    __syncthreads();
#pragma unroll
    for (int i = y; i < 32; i += 8)
        vT[((long long)(b * H_DIM + h) * VD + d0 + i) * S_DIM + s0 + x] = tf32f(t[x][i]);
}

// ---------------- merged rmsnorm (qa rows then ckv rows) ----------------
__global__ void rmsnorm2_kernel(const float* __restrict__ x0, const float* __restrict__ w0,
                                float* __restrict__ y0,
                                const float* __restrict__ x1, const float* __restrict__ w1,
                                float* __restrict__ y1)
{
    const float4 *xr, *wr; float4* yr; int N;
    long long row;
    if (blockIdx.x < T_DIM) {
        row = blockIdx.x;
        N = Q_RANK;
        xr = (const float4*)x0 + row * (Q_RANK >> 2); wr = (const float4*)w0;
        yr = (float4*)y0 + row * (Q_RANK >> 2);
    } else {
        row = blockIdx.x - T_DIM;
        N = KV_RANK;
        xr = (const float4*)x1 + row * ((KV_RANK + ROPE) >> 2); wr = (const float4*)w1;
        yr = (float4*)y1 + row * (KV_RANK >> 2);
    }
    int tid = threadIdx.x;
    int nv = N >> 2;

    float ss = 0.f;
    for (int i = tid; i < nv; i += 256) {
        float4 v = xr[i];
        ss += v.x * v.x + v.y * v.y + v.z * v.z + v.w * v.w;
    }
    __shared__ float red[256];
    red[tid] = ss; __syncthreads();
#pragma unroll
    for (int s = 128; s > 0; s >>= 1) {
        if (tid < s) red[tid] += red[tid + s];
        __syncthreads();
    }
    float sc = rsqrtf(red[0] / (float)N + EPS_F);
    for (int i = tid; i < nv; i += 256) {
        float4 v = xr[i], ww = wr[i];
        v.x = tf32f(v.x * sc * ww.x); v.y = tf32f(v.y * sc * ww.y);
        v.z = tf32f(v.z * sc * ww.z); v.w = tf32f(v.w * sc * ww.w);
        yr[i] = v;
    }
}

// ---------------- launch ----------------
extern "C" void kernel_launch(void* const* d_in, const int* in_sizes, int n_in,
                              void* d_out, int out_size)
{
    const float* hidden   = (const float*)d_in[0];
    const float* cosp     = (const float*)d_in[1];
    const float* sinp     = (const float*)d_in[2];
    const float* w_q_a    = (const float*)d_in[3];
    const float* q_a_ln_w = (const float*)d_in[4];
    const float* w_q_b    = (const float*)d_in[5];
    const float* w_kv_a   = (const float*)d_in[6];
    const float* kv_a_ln_w= (const float*)d_in[7];
    const float* w_kv_b   = (const float*)d_in[8];
    const float* w_o      = (const float*)d_in[9];
    float* out = (float*)d_out;

    float *p_qa, *p_qan, *p_q, *p_ckv, *p_ckvn, *p_kv, *p_key, *p_attn;
    float *p_wqaT, *p_wqbT, *p_wkvaT, *p_wkvbT, *p_woT, *p_vT;
    cudaGetSymbolAddress((void**)&p_qa,     g_qa);
    cudaGetSymbolAddress((void**)&p_qan,    g_qan);
    cudaGetSymbolAddress((void**)&p_q,      g_q);
    cudaGetSymbolAddress((void**)&p_ckv,    g_ckv);
    cudaGetSymbolAddress((void**)&p_ckvn,   g_ckvn);
    cudaGetSymbolAddress((void**)&p_kv,     g_kv);
    cudaGetSymbolAddress((void**)&p_key,    g_key);
    cudaGetSymbolAddress((void**)&p_attn,   g_attn);
    cudaGetSymbolAddress((void**)&p_wqaT,   g_wqaT);
    cudaGetSymbolAddress((void**)&p_wqbT,   g_wqbT);
    cudaGetSymbolAddress((void**)&p_wkvaT,  g_wkvaT);
    cudaGetSymbolAddress((void**)&p_wkvbT,  g_wkvbT);
    cudaGetSymbolAddress((void**)&p_woT,    g_woT);
    cudaGetSymbolAddress((void**)&p_vT,     g_vT);

    const int SMEM = 2 * STG_B;   // 55296
    cudaFuncSetAttribute(gemm2_kernel<true, true>,   cudaFuncAttributeMaxDynamicSharedMemorySize, SMEM);
    cudaFuncSetAttribute(gemm2_kernel<false, false>, cudaFuncAttributeMaxDynamicSharedMemorySize, SMEM);
    cudaFuncSetAttribute(flash_kernel, cudaFuncAttributeMaxDynamicSharedMemorySize, FL_SMEM);

    // 1. pre-pass: weight transposes only
    prep_kernel<<<14976, 256>>>(w_q_a, w_q_b, w_kv_a, w_kv_b, w_o,
                                p_wqaT, p_wqbT, p_wkvaT, p_wkvbT, p_woT);

    // 2. G1: qa = hidden@wqaT (24 tiles) || ckv = hidden@wkvaT (9 tiles); A tf32-rounded in-kernel
    gemm2_kernel<true, true><<<dim3(33, T_DIM/128, 1), 128, SMEM>>>(
        hidden, p_wqaT,  p_qa,  D_DIM, D_DIM, D_DIM, Q_RANK, 0,
        hidden, p_wkvaT, p_ckv, D_DIM, D_DIM, D_DIM, KV_RANK+ROPE, 0,
        24);

    // 3. merged rmsnorm (qa -> qan, ckv[:512] -> ckvn)
    rmsnorm2_kernel<<<2 * T_DIM, 256>>>(p_qa, q_a_ln_w, p_qan,
                                        p_ckv, kv_a_ln_w, p_ckvn);

    // 4. G2: q = qan@wqbT (48 tiles, rounded out) || kv = ckvn@wkvbT (64 tiles)
    gemm2_kernel<false, false><<<dim3(112, T_DIM/128, 1), 128, SMEM>>>(
        p_qan,  p_wqbT,  p_q,  Q_RANK,  Q_RANK,  Q_RANK,  H_DIM*HEAD, 1,
        p_ckvn, p_wkvbT, p_kv, KV_RANK, KV_RANK, KV_RANK, H_DIM*256,  0,
        48);

    // 5. merged post-pass: rope q + build key + V transpose
    post_kernel<<<4 * T_DIM, 256>>>(p_q, p_kv, p_ckv, cosp, sinp, p_key, p_vT);

    // 6. fused flash attention -> g_attn
    flash_kernel<<<dim3(S_DIM/128, B_DIM*H_DIM), 256, FL_SMEM>>>(p_q, p_key, p_vT, p_attn);

    // 7. out = attn @ woT (32 tiles)
    gemm2_kernel<false, false><<<dim3(32, T_DIM/128, 1), 128, SMEM>>>(
        p_attn, p_woT, out, H_DIM*VD, H_DIM*VD, H_DIM*VD, D_DIM, 0,
        p_attn, p_woT, out, H_DIM*VD, H_DIM*VD, H_DIM*VD, D_DIM, 0,
        32);
}

// round 16
// speedup vs baseline: 1.0677x; 1.0096x over previous
#include <cuda_runtime.h>
#include <cuda_bf16.h>
#include <math.h>

// ---------------- problem constants ----------------
#define T_DIM 4096
#define D_DIM 2048
#define H_DIM 16
#define NOPE 128
#define ROPE 64
#define VD 128
#define KV_RANK 512
#define HEAD 192               // NOPE + ROPE
#define Q_RANK 1536
#define B_DIM 2
#define S_DIM 2048
#define SCALE_F 0.072168783648703220563f   // 192^-0.5
#define EPS_F 1e-6f

// ---------------- scratch ----------------
__device__ float g_qa  [(long long)T_DIM * Q_RANK];
__device__ float g_qan [(long long)T_DIM * Q_RANK];
__device__ float g_q   [(long long)T_DIM * H_DIM * HEAD];
__device__ float g_ckv [(long long)T_DIM * (KV_RANK + ROPE)];
__device__ float g_ckvn[(long long)T_DIM * KV_RANK];
__device__ float g_kv  [(long long)T_DIM * H_DIM * (NOPE + VD)];
__device__ float g_key [(long long)T_DIM * H_DIM * HEAD];
__device__ float g_attn[(long long)T_DIM * H_DIM * VD];
// transposed (tf32-rounded) weights / V
__device__ float g_wqaT [(long long)Q_RANK * D_DIM];
__device__ float g_wqbT [(long long)H_DIM * HEAD * Q_RANK];
__device__ float g_wkvaT[(long long)(KV_RANK + ROPE) * D_DIM];
__device__ float g_wkvbT[(long long)H_DIM * (NOPE + VD) * KV_RANK];
__device__ float g_woT  [(long long)D_DIM * H_DIM * VD];
__device__ float g_vT   [(long long)B_DIM * H_DIM * VD * S_DIM];

__device__ __forceinline__ float tf32f(float f) {
    unsigned u; asm("cvt.rna.tf32.f32 %0, %1;" : "=r"(u) : "f"(f));
    return __uint_as_float(u);
}
__device__ __forceinline__ unsigned tf32r(unsigned u) {
    unsigned o; asm("cvt.rna.tf32.f32 %0, %1;" : "=r"(o) : "f"(__uint_as_float(u)));
    return o;
}
__device__ __forceinline__ void cp16(unsigned dst, const void* src) {
    asm volatile("cp.async.cg.shared.global [%0], [%1], 16;\n"
                 :: "r"(dst), "l"(src));
}
__device__ __forceinline__ void ldsm4(unsigned& r0, unsigned& r1, unsigned& r2, unsigned& r3,
                                      unsigned addr) {
    asm volatile("ldmatrix.sync.aligned.m8n8.x4.shared.b16 {%0,%1,%2,%3}, [%4];"
                 : "=r"(r0), "=r"(r1), "=r"(r2), "=r"(r3) : "r"(addr));
}
#define MMA_TF32(acc, a, b0, b1) \
    asm volatile("mma.sync.aligned.m16n8k8.row.col.f32.tf32.tf32.f32 " \
                 "{%0,%1,%2,%3},{%4,%5,%6,%7},{%8,%9},{%0,%1,%2,%3};" \
                 : "+f"(acc[0]), "+f"(acc[1]), "+f"(acc[2]), "+f"(acc[3]) \
                 : "r"(a[0]), "r"(a[1]), "r"(a[2]), "r"(a[3]), "r"(b0), "r"(b1))

// ---------------- NT tf32 GEMM body (R12/R15 proven): 128x64x32, 4 warps ----------------
#define STG_B 27648
#define BOFF_B 18432

template<bool RA>
__device__ __forceinline__ void gemm_body(
    const float* __restrict__ A, const float* __restrict__ B, float* __restrict__ C,
    int K, int lda, int ldb, int ldc, int m0, int n0, int round_out, char* smc)
{
    float* sm = (float*)smc;
    int nIter = K >> 5;
    int tid  = threadIdx.x;
    int lane = tid & 31;
    int wid  = tid >> 5;
    int wm   = wid & 1;
    int wn   = wid >> 1;

    unsigned sbase = (unsigned)__cvta_generic_to_shared(sm);
    int lrow = tid >> 3;
    int lc   = tid & 7;

    auto issue = [&](int itk) {
        int k0 = itk << 5;
        unsigned sb = sbase + (unsigned)(itk & 1) * STG_B;
        const float* Ap = A + (long long)(m0 + lrow) * lda + k0 + lc * 4;
        unsigned ad = sb + lrow * 144 + lc * 16;
#pragma unroll
        for (int it = 0; it < 8; it++)
            cp16(ad + it * (16 * 144), Ap + (long long)(it * 16) * lda);
        const float* Bp = B + (long long)(n0 + lrow) * ldb + k0 + lc * 4;
        unsigned bd = sb + BOFF_B + lrow * 144 + lc * 16;
#pragma unroll
        for (int it = 0; it < 4; it++)
            cp16(bd + it * (16 * 144), Bp + (long long)(it * 16) * ldb);
        asm volatile("cp.async.commit_group;");
    };

    issue(0);

    unsigned aoff[4], boff[2];
#pragma unroll
    for (int i = 0; i < 4; i++) {
        int R = wm * 64 + i * 16 + (lane & 15);
        aoff[i] = (unsigned)(R * 144 + (lane >> 4) * 16);
    }
#pragma unroll
    for (int jp = 0; jp < 2; jp++) {
        int R = wn * 32 + jp * 16 + ((lane >> 4) & 1) * 8 + (lane & 7);
        boff[jp] = (unsigned)(BOFF_B + R * 144 + ((lane >> 3) & 1) * 16);
    }

    float acc[4][4][4];
#pragma unroll
    for (int i = 0; i < 4; i++)
#pragma unroll
        for (int j = 0; j < 4; j++)
#pragma unroll
            for (int r = 0; r < 4; r++) acc[i][j][r] = 0.f;

    unsigned af[2][4][4], bf[2][2][4];

    for (int i = 0; i < nIter; i++) {
        if (i + 1 < nIter) {
            issue(i + 1);
            asm volatile("cp.async.wait_group 1;");
        } else {
            asm volatile("cp.async.wait_group 0;");
        }
        __syncthreads();

        unsigned sb = sbase + (unsigned)(i & 1) * STG_B;
#pragma unroll
        for (int ii = 0; ii < 4; ii++)
            ldsm4(af[0][ii][0], af[0][ii][1], af[0][ii][2], af[0][ii][3], sb + aoff[ii]);
        if (RA) {
#pragma unroll
            for (int ii = 0; ii < 4; ii++)
#pragma unroll
                for (int r = 0; r < 4; r++) af[0][ii][r] = tf32r(af[0][ii][r]);
        }
#pragma unroll
        for (int jp = 0; jp < 2; jp++)
            ldsm4(bf[0][jp][0], bf[0][jp][1], bf[0][jp][2], bf[0][jp][3], sb + boff[jp]);

#pragma unroll
        for (int ks = 0; ks < 4; ks++) {
            int cur = ks & 1, nxt = cur ^ 1;
            if (ks < 3) {
#pragma unroll
                for (int ii = 0; ii < 4; ii++)
                    ldsm4(af[nxt][ii][0], af[nxt][ii][1], af[nxt][ii][2], af[nxt][ii][3],
                          sb + aoff[ii] + (ks + 1) * 32);
                if (RA) {
#pragma unroll
                    for (int ii = 0; ii < 4; ii++)
#pragma unroll
                        for (int r = 0; r < 4; r++) af[nxt][ii][r] = tf32r(af[nxt][ii][r]);
                }
#pragma unroll
                for (int jp = 0; jp < 2; jp++)
                    ldsm4(bf[nxt][jp][0], bf[nxt][jp][1], bf[nxt][jp][2], bf[nxt][jp][3],
                          sb + boff[jp] + (ks + 1) * 32);
            }
#pragma unroll
            for (int ii = 0; ii < 4; ii++)
#pragma unroll
                for (int j = 0; j < 4; j++) {
                    unsigned b0 = bf[cur][j >> 1][(j & 1) * 2];
                    unsigned b1 = bf[cur][j >> 1][(j & 1) * 2 + 1];
                    MMA_TF32(acc[ii][j], af[cur][ii], b0, b1);
                }
        }
        __syncthreads();
    }

    int gr = lane >> 2, tg = lane & 3;
#pragma unroll
    for (int i = 0; i < 4; i++) {
#pragma unroll
        for (int j = 0; j < 4; j++) {
            long long r0 = m0 + wm * 64 + i * 16 + gr;
            int c = n0 + wn * 32 + j * 8 + 2 * tg;
            float v0 = acc[i][j][0], v1 = acc[i][j][1];
            float v2 = acc[i][j][2], v3 = acc[i][j][3];
            if (round_out) { v0 = tf32f(v0); v1 = tf32f(v1); v2 = tf32f(v2); v3 = tf32f(v3); }
            *(float2*)(C + r0 * ldc + c)       = make_float2(v0, v1);
            *(float2*)(C + (r0 + 8) * ldc + c) = make_float2(v2, v3);
        }
    }
}

template<bool RA0, bool RA1>
__global__ void __launch_bounds__(128, 3)
gemm2_kernel(const float* A0, const float* B0, float* C0,
             int K0, int lda0, int ldb0, int ldc0, int ro0,
             const float* A1, const float* B1, float* C1,
             int K1, int lda1, int ldb1, int ldc1, int ro1,
             int split)
{
    extern __shared__ char smc[];
    int m0 = blockIdx.y * 128;
    int bx = blockIdx.x;
    if (bx < split)
        gemm_body<RA0>(A0, B0, C0, K0, lda0, ldb0, ldc0, m0, bx * 64, ro0, smc);
    else
        gemm_body<RA1>(A1, B1, C1, K1, lda1, ldb1, ldc1, m0, (bx - split) * 64, ro1, smc);
}

// ---------------- flash attention (R11/R12/R15, proven) ----------------
#define FL_QB 0u
#define FL_KB 100352u
#define FL_V0 150528u
#define FL_V1 185344u
#define FL_SMEM 220160

__global__ void __launch_bounds__(256)
flash_kernel(const float* __restrict__ Qg, const float* __restrict__ Kg,
             const float* __restrict__ Vt, float* __restrict__ O)
{
    extern __shared__ float sm[];
    unsigned sb = (unsigned)__cvta_generic_to_shared(sm);
    int qi = (int)gridDim.x - 1 - (int)blockIdx.x;
    int bh = blockIdx.y;
    int b = bh >> 4, h = bh & 15;
    int q0 = qi * 128;
    int tid = threadIdx.x, lane = tid & 31, wid = tid >> 5;
    int wm = wid;
    int gr = lane >> 2, tg = lane & 3;

    const float* Qp = Qg + ((long long)(b * S_DIM + q0)) * (H_DIM * HEAD) + h * HEAD;
    const float* Kp = Kg + ((long long)(b * S_DIM)) * (H_DIM * HEAD) + h * HEAD;
    const float* Vp = Vt + ((long long)(b * H_DIM + h)) * VD * S_DIM;

    auto loadK = [&](int j) {
        const float* src = Kp + (long long)(j * 64) * (H_DIM * HEAD);
#pragma unroll
        for (int t = 0; t < 12; t++) {
            int idx = tid + t * 256;
            int r = idx / 48, c = idx % 48;
            cp16(sb + FL_KB + r * 784 + c * 16, src + (long long)r * (H_DIM * HEAD) + c * 4);
        }
    };
    auto loadV = [&](int j, int buf) {
        const float* src = Vp + j * 64;
        unsigned dst = sb + (buf ? FL_V1 : FL_V0);
#pragma unroll
        for (int t = 0; t < 8; t++) {
            int idx = tid + t * 256;
            int r = idx >> 4, c = idx & 15;
            cp16(dst + r * 272 + c * 16, src + (long long)r * S_DIM + c * 4);
        }
    };

#pragma unroll
    for (int t = 0; t < 24; t++) {
        int idx = tid + t * 256;
        int r = idx / 48, c = idx % 48;
        cp16(sb + FL_QB + r * 784 + c * 16, Qp + (long long)r * (H_DIM * HEAD) + c * 4);
    }
    loadK(0);
    asm volatile("cp.async.commit_group;");
    loadV(0, 0);
    asm volatile("cp.async.commit_group;");

    unsigned aoffQ, aoffP, boffK[4], boffV[8];
    {
        int R = wm * 16 + (lane & 15);
        aoffQ = (unsigned)(FL_QB + R * 784 + (lane >> 4) * 16);
        aoffP = (unsigned)(R * 272 + (lane >> 4) * 16);
    }
#pragma unroll
    for (int jp = 0; jp < 4; jp++) {
        int R = jp * 16 + ((lane >> 4) & 1) * 8 + (lane & 7);
        boffK[jp] = (unsigned)(FL_KB + R * 784 + ((lane >> 3) & 1) * 16);
    }
#pragma unroll
    for (int jp = 0; jp < 8; jp++) {
        int R = jp * 16 + ((lane >> 4) & 1) * 8 + (lane & 7);
        boffV[jp] = (unsigned)(R * 272 + ((lane >> 3) & 1) * 16);
    }

    float oacc[16][4];
#pragma unroll
    for (int jo = 0; jo < 16; jo++)
#pragma unroll
        for (int r = 0; r < 4; r++) oacc[jo][r] = 0.f;
    float m_[2] = {-1e30f, -1e30f};
    float l_[2] = {0.f, 0.f};

    int jmax = 2 * qi + 1;
    for (int j = 0; j <= jmax; j++) {
        asm volatile("cp.async.wait_group 1;");
        __syncthreads();

        float sacc[8][4];
#pragma unroll
        for (int jj = 0; jj < 8; jj++)
#pragma unroll
            for (int r = 0; r < 4; r++) sacc[jj][r] = 0.f;
        {
            unsigned af[4], bfk[4][4];
#pragma unroll
            for (int ks = 0; ks < 24; ks++) {
                ldsm4(af[0], af[1], af[2], af[3], sb + aoffQ + ks * 32);
#pragma unroll
                for (int jp = 0; jp < 4; jp++)
                    ldsm4(bfk[jp][0], bfk[jp][1], bfk[jp][2], bfk[jp][3], sb + boffK[jp] + ks * 32);
#pragma unroll
                for (int jj = 0; jj < 8; jj++) {
                    unsigned b0 = bfk[jj >> 1][(jj & 1) * 2];
                    unsigned b1 = bfk[jj >> 1][(jj & 1) * 2 + 1];
                    MMA_TF32(sacc[jj], af, b0, b1);
                }
            }
        }
        __syncthreads();
        if (j < jmax) loadK(j + 1);
        asm volatile("cp.async.commit_group;");

        bool mb = (j >= 2 * qi);
        float rm[2] = {-1e30f, -1e30f};
#pragma unroll
        for (int jj = 0; jj < 8; jj++)
#pragma unroll
            for (int k4 = 0; k4 < 4; k4++) {
                float t = sacc[jj][k4] * SCALE_F;
                if (mb) {
                    int col = j * 64 + jj * 8 + 2 * tg + (k4 & 1);
                    int row = q0 + wm * 16 + gr + 8 * (k4 >> 1);
                    if (col > row) t = -1e30f;
                }
                sacc[jj][k4] = t;
                rm[k4 >> 1] = fmaxf(rm[k4 >> 1], t);
            }
#pragma unroll
        for (int s = 0; s < 2; s++) {
            float v = rm[s];
            v = fmaxf(v, __shfl_xor_sync(0xffffffffu, v, 1));
            v = fmaxf(v, __shfl_xor_sync(0xffffffffu, v, 2));
            rm[s] = v;
        }
        float sf[2], rs[2] = {0.f, 0.f};
#pragma unroll
        for (int s = 0; s < 2; s++) {
            float mn = fmaxf(m_[s], rm[s]);
            sf[s] = __expf(m_[s] - mn);
            m_[s] = mn;
        }
#pragma unroll
        for (int jj = 0; jj < 8; jj++)
#pragma unroll
            for (int k4 = 0; k4 < 4; k4++) {
                float p = __expf(sacc[jj][k4] - m_[k4 >> 1]);
                sacc[jj][k4] = p;
                rs[k4 >> 1] += p;
            }
#pragma unroll
        for (int s = 0; s < 2; s++) {
            float v = rs[s];
            v += __shfl_xor_sync(0xffffffffu, v, 1);
            v += __shfl_xor_sync(0xffffffffu, v, 2);
            l_[s] = l_[s] * sf[s] + v;
        }
#pragma unroll
        for (int jo = 0; jo < 16; jo++) {
            oacc[jo][0] *= sf[0]; oacc[jo][1] *= sf[0];
            oacc[jo][2] *= sf[1]; oacc[jo][3] *= sf[1];
        }

        unsigned pB = sb + (((j + 1) & 1) ? FL_V1 : FL_V0);
#pragma unroll
        for (int jj = 0; jj < 8; jj++) {
            int colb = (jj * 8 + 2 * tg) * 4;
            int r0 = wm * 16 + gr;
            float2 v0 = make_float2(tf32f(sacc[jj][0]), tf32f(sacc[jj][1]));
            float2 v1 = make_float2(tf32f(sacc[jj][2]), tf32f(sacc[jj][3]));
            asm volatile("st.shared.v2.f32 [%0], {%1, %2};" :: "r"(pB + r0 * 272 + colb), "f"(v0.x), "f"(v0.y));
            asm volatile("st.shared.v2.f32 [%0], {%1, %2};" :: "r"(pB + (r0 + 8) * 272 + colb), "f"(v1.x), "f"(v1.y));
        }
        asm volatile("cp.async.wait_group 1;");
        __syncthreads();

        {
            unsigned vB = sb + ((j & 1) ? FL_V1 : FL_V0);
            unsigned afp[4], bfv[8][4];
#pragma unroll
            for (int ks = 0; ks < 8; ks++) {
                ldsm4(afp[0], afp[1], afp[2], afp[3], pB + aoffP + ks * 32);
#pragma unroll
                for (int jp = 0; jp < 8; jp++)
                    ldsm4(bfv[jp][0], bfv[jp][1], bfv[jp][2], bfv[jp][3], vB + boffV[jp] + ks * 32);
#pragma unroll
                for (int jo = 0; jo < 16; jo++) {
                    unsigned b0 = bfv[jo >> 1][(jo & 1) * 2];
                    unsigned b1 = bfv[jo >> 1][(jo & 1) * 2 + 1];
                    MMA_TF32(oacc[jo], afp, b0, b1);
                }
            }
        }
        __syncthreads();
        if (j < jmax) loadV(j + 1, (j + 1) & 1);
        asm volatile("cp.async.commit_group;");
    }

    float il[2] = {1.0f / l_[0], 1.0f / l_[1]};
#pragma unroll
    for (int jo = 0; jo < 16; jo++) {
        long long r0 = (long long)(b * S_DIM + q0 + wm * 16 + gr);
        int c = jo * 8 + 2 * tg;
        float* d0 = O + r0 * (H_DIM * VD) + h * VD + c;
        float* d1 = d0 + 8LL * (H_DIM * VD);
        *(float2*)d0 = make_float2(tf32f(oacc[jo][0] * il[0]),
                                   tf32f(oacc[jo][1] * il[0]));
        *(float2*)d1 = make_float2(tf32f(oacc[jo][2] * il[1]),
                                   tf32f(oacc[jo][3] * il[1]));
    }
}

// ---------------- pre-pass: 5 weight transposes (vectorized, conflict-free) ----------------
__global__ void __launch_bounds__(256)
prep_kernel(const float* __restrict__ w_q_a, const float* __restrict__ w_q_b,
            const float* __restrict__ w_kv_a, const float* __restrict__ w_kv_b,
            const float* __restrict__ w_o,
            float* __restrict__ wqaT, float* __restrict__ wqbT,
            float* __restrict__ wkvaT, float* __restrict__ wkvbT,
            float* __restrict__ woT)
{
    int tile = blockIdx.x;
    int tid = threadIdx.x;

    const float* in; float* out; int K, N, idx;
    if (tile < 3072)       { in = w_q_a;  out = wqaT;  K = 2048; N = 1536; idx = tile; }
    else if (tile < 7680)  { in = w_q_b;  out = wqbT;  K = 1536; N = 3072; idx = tile - 3072; }
    else if (tile < 8832)  { in = w_kv_a; out = wkvaT; K = 2048; N = 576;  idx = tile - 7680; }
    else if (tile < 10880) { in = w_kv_b; out = wkvbT; K = 512;  N = 4096; idx = tile - 8832; }
    else                   { in = w_o;    out = woT;   K = 2048; N = 2048; idx = tile - 10880; }

    int nx = N >> 5;
    int n0 = (idx % nx) * 32;
    int k0 = (idx / nx) * 32;

    __shared__ float t[32][33];
    int r  = tid >> 3;            // 0..31 (k row)
    int cq = (tid & 7) * 4;       // n quad
    float4 v = *(const float4*)(in + (long long)(k0 + r) * N + n0 + cq);
    t[r][cq + 0] = v.x; t[r][cq + 1] = v.y; t[r][cq + 2] = v.z; t[r][cq + 3] = v.w;
    __syncthreads();
    int n  = tid >> 3;            // out row (n)
    int kq = (tid & 7) * 4;       // k quad
    float4 o;
    o.x = tf32f(t[kq + 0][n]); o.y = tf32f(t[kq + 1][n]);
    o.z = tf32f(t[kq + 2][n]); o.w = tf32f(t[kq + 3][n]);
    *(float4*)(out + (long long)(n0 + n) * K + k0 + kq) = o;
}

// ---------------- merged post-pass: rope_q + build_key + vtrans (vectorized) ----------------
__global__ void __launch_bounds__(256)
post_kernel(float* __restrict__ q, const float* __restrict__ kv,
            const float* __restrict__ ckv,
            const float* __restrict__ cosp, const float* __restrict__ sinp,
            float* __restrict__ key, float* __restrict__ vT)
{
    int bx = blockIdx.x;
    int tid = threadIdx.x;

    if (bx < T_DIM) {                       // rope q (in place, rounded)
        int t = bx;
#pragma unroll
        for (int half = 0; half < 2; half++) {
            int it = tid + half * 256;      // 0..511
            int h = it >> 5, i = it & 31;
            float* pe = q + ((long long)t * H_DIM + h) * HEAD + NOPE;
            float e = pe[2 * i], o = pe[2 * i + 1];
            float c = cosp[t * 32 + i], s = sinp[t * 32 + i];
            __syncwarp();
            pe[i]      = tf32f(e * c - o * s);
            pe[32 + i] = tf32f(o * c + e * s);
        }
        return;
    }
    if (bx < 2 * T_DIM) {                   // build key (rounded, float4 nope copy)
        int t = bx - T_DIM;
        long long base = (long long)t * (H_DIM * HEAD);
        const float4* kvr4 = (const float4*)(kv + (long long)t * (H_DIM * 256));
#pragma unroll
        for (int p = 0; p < 2; p++) {
            int idx = tid + p * 256;        // 0..511 float4s (16 heads x 32)
            int h = idx >> 5, qd = idx & 31;
            float4 v = kvr4[h * 64 + qd];
            v.x = tf32f(v.x); v.y = tf32f(v.y); v.z = tf32f(v.z); v.w = tf32f(v.w);
            *(float4*)(key + base + h * HEAD + qd * 4) = v;
        }
        const float* pe = ckv + (long long)t * (KV_RANK + ROPE) + KV_RANK;
#pragma unroll
        for (int half = 0; half < 2; half++) {
            int it = tid + half * 256;
            int h = it >> 5, i = it & 31;
            float e = pe[2 * i], o = pe[2 * i + 1];
            float c = cosp[t * 32 + i], s = sinp[t * 32 + i];
            key[base + h * HEAD + NOPE + i]      = tf32f(e * c - o * s);
            key[base + h * HEAD + NOPE + 32 + i] = tf32f(o * c + e * s);
        }
        return;
    }
    // vtrans: 8192 tiles (sx 64, dy 4, z 32), vectorized conflict-free 32x32
    int vb = bx - 2 * T_DIM;
    int sx = vb & 63, dy = (vb >> 6) & 3, z = vb >> 8;
    int b = z >> 4, h = z & 15;
    int s0 = sx * 32, d0 = dy * 32;
    __shared__ float t[32][33];
    int r  = tid >> 3;            // s row
    int cq = (tid & 7) * 4;       // d quad
    float4 v = *(const float4*)(kv + (long long)(b * S_DIM + s0 + r) * (H_DIM * 256)
                                + h * 256 + 128 + d0 + cq);
    t[r][cq + 0] = v.x; t[r][cq + 1] = v.y; t[r][cq + 2] = v.z; t[r][cq + 3] = v.w;
    __syncthreads();
    int d  = tid >> 3;            // out row (d)
    int kq = (tid & 7) * 4;       // s quad
    float4 o;
    o.x = tf32f(t[kq + 0][d]); o.y = tf32f(t[kq + 1][d]);
    o.z = tf32f(t[kq + 2][d]); o.w = tf32f(t[kq + 3][d]);
    *(float4*)(vT + ((long long)(b * H_DIM + h) * VD + d0 + d) * S_DIM + s0 + kq) = o;
}

// ---------------- merged rmsnorm (qa rows then ckv rows) ----------------
__global__ void rmsnorm2_kernel(const float* __restrict__ x0, const float* __restrict__ w0,
                                float* __restrict__ y0,
                                const float* __restrict__ x1, const float* __restrict__ w1,
                                float* __restrict__ y1)
{
    const float4 *xr, *wr; float4* yr; int N;
    long long row;
    if (blockIdx.x < T_DIM) {
        row = blockIdx.x;
        N = Q_RANK;
        xr = (const float4*)x0 + row * (Q_RANK >> 2); wr = (const float4*)w0;
        yr = (float4*)y0 + row * (Q_RANK >> 2);
    } else {
        row = blockIdx.x - T_DIM;
        N = KV_RANK;
        xr = (const float4*)x1 + row * ((KV_RANK + ROPE) >> 2); wr = (const float4*)w1;
        yr = (float4*)y1 + row * (KV_RANK >> 2);
    }
    int tid = threadIdx.x;
    int nv = N >> 2;

    float ss = 0.f;
    for (int i = tid; i < nv; i += 256) {
        float4 v = xr[i];
        ss += v.x * v.x + v.y * v.y + v.z * v.z + v.w * v.w;
    }
    __shared__ float red[256];
    red[tid] = ss; __syncthreads();
#pragma unroll
    for (int s = 128; s > 0; s >>= 1) {
        if (tid < s) red[tid] += red[tid + s];
        __syncthreads();
    }
    float sc = rsqrtf(red[0] / (float)N + EPS_F);
    for (int i = tid; i < nv; i += 256) {
        float4 v = xr[i], ww = wr[i];
        v.x = tf32f(v.x * sc * ww.x); v.y = tf32f(v.y * sc * ww.y);
        v.z = tf32f(v.z * sc * ww.z); v.w = tf32f(v.w * sc * ww.w);
        yr[i] = v;
    }
}

// ---------------- launch ----------------
extern "C" void kernel_launch(void* const* d_in, const int* in_sizes, int n_in,
                              void* d_out, int out_size)
{
    const float* hidden   = (const float*)d_in[0];
    const float* cosp     = (const float*)d_in[1];
    const float* sinp     = (const float*)d_in[2];
    const float* w_q_a    = (const float*)d_in[3];
    const float* q_a_ln_w = (const float*)d_in[4];
    const float* w_q_b    = (const float*)d_in[5];
    const float* w_kv_a   = (const float*)d_in[6];
    const float* kv_a_ln_w= (const float*)d_in[7];
    const float* w_kv_b   = (const float*)d_in[8];
    const float* w_o      = (const float*)d_in[9];
    float* out = (float*)d_out;

    float *p_qa, *p_qan, *p_q, *p_ckv, *p_ckvn, *p_kv, *p_key, *p_attn;
    float *p_wqaT, *p_wqbT, *p_wkvaT, *p_wkvbT, *p_woT, *p_vT;
    cudaGetSymbolAddress((void**)&p_qa,     g_qa);
    cudaGetSymbolAddress((void**)&p_qan,    g_qan);
    cudaGetSymbolAddress((void**)&p_q,      g_q);
    cudaGetSymbolAddress((void**)&p_ckv,    g_ckv);
    cudaGetSymbolAddress((void**)&p_ckvn,   g_ckvn);
    cudaGetSymbolAddress((void**)&p_kv,     g_kv);
    cudaGetSymbolAddress((void**)&p_key,    g_key);
    cudaGetSymbolAddress((void**)&p_attn,   g_attn);
    cudaGetSymbolAddress((void**)&p_wqaT,   g_wqaT);
    cudaGetSymbolAddress((void**)&p_wqbT,   g_wqbT);
    cudaGetSymbolAddress((void**)&p_wkvaT,  g_wkvaT);
    cudaGetSymbolAddress((void**)&p_wkvbT,  g_wkvbT);
    cudaGetSymbolAddress((void**)&p_woT,    g_woT);
    cudaGetSymbolAddress((void**)&p_vT,     g_vT);

    const int SMEM = 2 * STG_B;   // 55296
    cudaFuncSetAttribute(gemm2_kernel<true, true>,   cudaFuncAttributeMaxDynamicSharedMemorySize, SMEM);
    cudaFuncSetAttribute(gemm2_kernel<false, false>, cudaFuncAttributeMaxDynamicSharedMemorySize, SMEM);
    cudaFuncSetAttribute(flash_kernel, cudaFuncAttributeMaxDynamicSharedMemorySize, FL_SMEM);

    // 1. pre-pass: weight transposes (vectorized)
    prep_kernel<<<14976, 256>>>(w_q_a, w_q_b, w_kv_a, w_kv_b, w_o,
                                p_wqaT, p_wqbT, p_wkvaT, p_wkvbT, p_woT);

    // 2. G1: qa = hidden@wqaT (24 tiles) || ckv = hidden@wkvaT (9 tiles); A tf32-rounded in-kernel
    gemm2_kernel<true, true><<<dim3(33, T_DIM/128, 1), 128, SMEM>>>(
        hidden, p_wqaT,  p_qa,  D_DIM, D_DIM, D_DIM, Q_RANK, 0,
        hidden, p_wkvaT, p_ckv, D_DIM, D_DIM, D_DIM, KV_RANK+ROPE, 0,
        24);

    // 3. merged rmsnorm (qa -> qan, ckv[:512] -> ckvn)
    rmsnorm2_kernel<<<2 * T_DIM, 256>>>(p_qa, q_a_ln_w, p_qan,
                                        p_ckv, kv_a_ln_w, p_ckvn);

    // 4. G2: q = qan@wqbT (48 tiles, rounded out) || kv = ckvn@wkvbT (64 tiles)
    gemm2_kernel<false, false><<<dim3(112, T_DIM/128, 1), 128, SMEM>>>(
        p_qan,  p_wqbT,  p_q,  Q_RANK,  Q_RANK,  Q_RANK,  H_DIM*HEAD, 1,
        p_ckvn, p_wkvbT, p_kv, KV_RANK, KV_RANK, KV_RANK, H_DIM*256,  0,
        48);

    // 5. merged post-pass: rope q + build key + V transpose (vectorized)
    post_kernel<<<4 * T_DIM, 256>>>(p_q, p_kv, p_ckv, cosp, sinp, p_key, p_vT);

    // 6. fused flash attention -> g_attn
    flash_kernel<<<dim3(S_DIM/128, B_DIM*H_DIM), 256, FL_SMEM>>>(p_q, p_key, p_vT, p_attn);

    // 7. out = attn @ woT (32 tiles)
    gemm2_kernel<false, false><<<dim3(32, T_DIM/128, 1), 128, SMEM>>>(
        p_attn, p_woT, out, H_DIM*VD, H_DIM*VD, H_DIM*VD, D_DIM, 0,
        p_attn, p_woT, out, H_DIM*VD, H_DIM*VD, H_DIM*VD, D_DIM, 0,
        32);
}